// round 2
// baseline (speedup 1.0000x reference)
#include <cuda_runtime.h>
#include <math.h>

#define B_   16
#define T_   24
#define H_   112
#define W_   112
#define CIN  3
#define F_   32
#define FOURF 128
#define HP   56
#define WPd  56
#define D_   (HP*WPd*F_)   // 100352

#define TS      8           // 8x8 output tile
#define XT      17          // x input tile (stride 2, halo)
#define XPITCH  18
#define HT      10          // h input tile (stride 1, halo)
#define HPITCH  24          // pitch 24: 4-row x 8-col warp footprint -> disjoint bank groups

// SMEM layout (floats):
#define UK_OFF   0
#define UK_SZ    (9*F_*FOURF)            // 36864
#define WK_OFF   (UK_OFF + UK_SZ)
#define WK_SZ    (9*CIN*FOURF)           // 3456
#define BI_OFF   (WK_OFF + WK_SZ)
#define BI_SZ    FOURF                   // 128
#define HS_OFF   (BI_OFF + BI_SZ)
#define HS_SZ    (F_*HT*HPITCH)          // 7680
#define XS_OFF   (HS_OFF + HS_SZ)
#define XS_SZ    (CIN*XT*XPITCH)         // 918
#define SM_TOTAL (XS_OFF + XS_SZ)        // 49046 floats = 196184 B
// z exchange region aliases h/x tiles (used after conv phase, behind a barrier)
#define ZS_OFF   HS_OFF                  // needs 64*128 = 8192 floats; HS_SZ+XS_SZ = 8598 >= 8192

// persistent state (device globals; no runtime allocation)
__device__ float g_h[2][(size_t)B_*HP*WPd*F_];
__device__ float g_c[(size_t)B_*HP*WPd*F_];

__global__ void zero_state_kernel() {
    const int n = B_*HP*WPd*F_;
    for (int i = blockIdx.x*blockDim.x + threadIdx.x; i < n; i += gridDim.x*blockDim.x) {
        g_h[0][i] = 0.0f;
        g_c[i]    = 0.0f;
    }
}

__global__ void __launch_bounds__(256, 1) step_kernel(
    const float* __restrict__ x,     // (B,T,H,W,CIN)
    const float* __restrict__ Wk,    // (3,3,CIN,128)
    const float* __restrict__ Uk,    // (3,3,F,128)
    const float* __restrict__ bias,  // (128,)
    float* __restrict__ out,         // (B,T,D)
    int t, int parity)
{
    extern __shared__ float sm[];
    float* uk_s = sm + UK_OFF;
    float* wk_s = sm + WK_OFF;
    float* b_s  = sm + BI_OFF;
    float* h_s  = sm + HS_OFF;
    float* x_s  = sm + XS_OFF;
    float* z_s  = sm + ZS_OFF;

    const int tid   = threadIdx.x;
    const int tileX = blockIdx.x;   // 0..6
    const int tileY = blockIdx.y;   // 0..6
    const int b     = blockIdx.z;   // 0..15

    const float* h_in  = g_h[parity];
    float*       h_out = g_h[parity ^ 1];

    // ---- load weights into smem (coalesced float4) ----
    {
        const float4* g4 = (const float4*)Uk;
        float4*       s4 = (float4*)uk_s;
        #pragma unroll 4
        for (int i = tid; i < UK_SZ/4; i += 256) s4[i] = g4[i];
    }
    {
        const float4* g4 = (const float4*)Wk;
        float4*       s4 = (float4*)wk_s;
        for (int i = tid; i < WK_SZ/4; i += 256) s4[i] = g4[i];
    }
    if (tid < FOURF) b_s[tid] = bias[tid];

    // ---- load x tile with halo (stride-2 SAME: pad_lo=0, pad_hi=1) ----
    {
        const int r0 = tileY * 16, c0 = tileX * 16;
        const float* xt = x + (((size_t)b * T_ + t) * H_) * (size_t)(W_ * CIN);
        for (int i = tid; i < XT*XT*CIN; i += 256) {
            int ci = i % CIN;
            int xx = (i / CIN) % XT;
            int yy = i / (CIN * XT);
            int gr = r0 + yy, gc = c0 + xx;
            float v = (gr < H_ && gc < W_) ? xt[((size_t)gr * W_ + gc) * CIN + ci] : 0.0f;
            x_s[ci * (XT*XPITCH) + yy * XPITCH + xx] = v;
        }
    }

    // ---- load h tile with halo (stride-1 SAME: pad 1) ----
    {
        const int hr0 = tileY * TS - 1, hc0 = tileX * TS - 1;
        const float* hb = h_in + (size_t)b * HP * WPd * F_;
        for (int i = tid; i < HT*HT*F_; i += 256) {
            int f  = i % F_;
            int xx = (i / F_) % HT;
            int yy = i / (F_ * HT);
            int gr = hr0 + yy, gc = hc0 + xx;
            float v = (gr >= 0 && gr < HP && gc >= 0 && gc < WPd)
                        ? hb[((size_t)gr * WPd + gc) * F_ + f] : 0.0f;
            h_s[f * (HT*HPITCH) + yy * HPITCH + xx] = v;
        }
    }
    __syncthreads();

    // ---- conv phase: each thread computes one spatial pos x 32 contiguous out channels ----
    const int pos = tid & 63;       // 0..63
    const int cq  = tid >> 6;       // 0..3 (warp-uniform -> weight LDS broadcast)
    const int py  = pos >> 3, px = pos & 7;

    float acc[32];
    {
        const float4* bb = (const float4*)&b_s[cq * 32];
        #pragma unroll
        for (int j4 = 0; j4 < 8; j4++) {
            float4 bv = bb[j4];
            acc[4*j4+0] = bv.x; acc[4*j4+1] = bv.y; acc[4*j4+2] = bv.z; acc[4*j4+3] = bv.w;
        }
    }

    // input conv (27 taps)
    #pragma unroll 1
    for (int kh = 0; kh < 3; kh++) {
        #pragma unroll 1
        for (int kw = 0; kw < 3; kw++) {
            #pragma unroll
            for (int ci = 0; ci < CIN; ci++) {
                float xv = x_s[ci * (XT*XPITCH) + (2*py + kh) * XPITCH + (2*px + kw)];
                const float4* w4 = (const float4*)&wk_s[((kh*3 + kw)*CIN + ci) * FOURF + cq*32];
                #pragma unroll
                for (int j4 = 0; j4 < 8; j4++) {
                    float4 w = w4[j4];
                    acc[4*j4+0] = fmaf(xv, w.x, acc[4*j4+0]);
                    acc[4*j4+1] = fmaf(xv, w.y, acc[4*j4+1]);
                    acc[4*j4+2] = fmaf(xv, w.z, acc[4*j4+2]);
                    acc[4*j4+3] = fmaf(xv, w.w, acc[4*j4+3]);
                }
            }
        }
    }

    // recurrent conv (288 taps)
    #pragma unroll 1
    for (int kh = 0; kh < 3; kh++) {
        #pragma unroll 1
        for (int kw = 0; kw < 3; kw++) {
            const float* hrow = &h_s[(py + kh) * HPITCH + (px + kw)];
            const float* ubase = &uk_s[(kh*3 + kw) * F_ * FOURF + cq*32];
            #pragma unroll 4
            for (int ci = 0; ci < F_; ci++) {
                float hv = hrow[ci * (HT*HPITCH)];
                const float4* w4 = (const float4*)(ubase + ci * FOURF);
                #pragma unroll
                for (int j4 = 0; j4 < 8; j4++) {
                    float4 w = w4[j4];
                    acc[4*j4+0] = fmaf(hv, w.x, acc[4*j4+0]);
                    acc[4*j4+1] = fmaf(hv, w.y, acc[4*j4+1]);
                    acc[4*j4+2] = fmaf(hv, w.z, acc[4*j4+2]);
                    acc[4*j4+3] = fmaf(hv, w.w, acc[4*j4+3]);
                }
            }
        }
    }

    // ---- exchange z through smem (aliases h/x tiles) ----
    __syncthreads();
    {
        float4* zdst = (float4*)&z_s[pos * FOURF + cq * 32];
        #pragma unroll
        for (int j4 = 0; j4 < 8; j4++)
            zdst[j4] = make_float4(acc[4*j4+0], acc[4*j4+1], acc[4*j4+2], acc[4*j4+3]);
    }
    __syncthreads();

    // ---- gate phase: 64 pos x 32 f = 2048 items over 256 threads ----
    {
        const int hp0 = tileY * TS, wp0 = tileX * TS;
        float* cb  = g_c + (size_t)b * HP * WPd * F_;
        float* hob = h_out + (size_t)b * HP * WPd * F_;
        float* ob  = out + ((size_t)b * T_ + t) * D_;
        #pragma unroll
        for (int k = tid; k < 2048; k += 256) {
            int p = k >> 5;
            int f = k & 31;
            float zi = z_s[p * FOURF +        f];
            float zf = z_s[p * FOURF + 32  +  f];
            float zc = z_s[p * FOURF + 64  +  f];
            float zo = z_s[p * FOURF + 96  +  f];
            float iG = __saturatef(fmaf(zi, 0.2f, 0.5f));
            float fG = __saturatef(fmaf(zf, 0.2f, 0.5f));
            float oG = __saturatef(fmaf(zo, 0.2f, 0.5f));
            int ppy = p >> 3, ppx = p & 7;
            size_t gidx = ((size_t)(hp0 + ppy) * WPd + (wp0 + ppx)) * F_ + f;
            float cn = fG * cb[gidx] + iG * tanhf(zc);
            float hn = oG * tanhf(cn);
            cb[gidx]  = cn;
            hob[gidx] = hn;
            ob[gidx]  = hn;
        }
    }
}

__global__ void __launch_bounds__(512) ln_kernel(
    float* __restrict__ y, const float* __restrict__ gamma, const float* __restrict__ beta)
{
    __shared__ float s_sum[16], s_sum2[16], s_stat[2];
    float* row = y + (size_t)blockIdx.x * D_;
    float s = 0.f, s2 = 0.f;
    for (int i = threadIdx.x; i < D_; i += blockDim.x) {
        float v = row[i];
        s += v;
        s2 = fmaf(v, v, s2);
    }
    #pragma unroll
    for (int o = 16; o > 0; o >>= 1) {
        s  += __shfl_xor_sync(0xFFFFFFFFu, s,  o);
        s2 += __shfl_xor_sync(0xFFFFFFFFu, s2, o);
    }
    int w = threadIdx.x >> 5, l = threadIdx.x & 31;
    if (l == 0) { s_sum[w] = s; s_sum2[w] = s2; }
    __syncthreads();
    if (w == 0) {
        s  = (l < 16) ? s_sum[l]  : 0.f;
        s2 = (l < 16) ? s_sum2[l] : 0.f;
        #pragma unroll
        for (int o = 8; o > 0; o >>= 1) {
            s  += __shfl_xor_sync(0xFFFFFFFFu, s,  o);
            s2 += __shfl_xor_sync(0xFFFFFFFFu, s2, o);
        }
        if (l == 0) {
            float mu  = s * (1.0f / D_);
            float var = s2 * (1.0f / D_) - mu * mu;
            s_stat[0] = mu;
            s_stat[1] = rsqrtf(var + 1e-3f);
        }
    }
    __syncthreads();
    float mu = s_stat[0], rs = s_stat[1];
    for (int i = threadIdx.x; i < D_; i += blockDim.x) {
        row[i] = (row[i] - mu) * rs * gamma[i] + beta[i];
    }
}

extern "C" void kernel_launch(void* const* d_in, const int* in_sizes, int n_in,
                              void* d_out, int out_size)
{
    const float* x     = (const float*)d_in[0];
    const float* Wk    = (const float*)d_in[1];
    const float* Uk    = (const float*)d_in[2];
    const float* bias  = (const float*)d_in[3];
    const float* gamma = (const float*)d_in[4];
    const float* beta  = (const float*)d_in[5];
    float* out = (float*)d_out;

    const int smemBytes = SM_TOTAL * (int)sizeof(float);   // 196184
    cudaFuncSetAttribute(step_kernel, cudaFuncAttributeMaxDynamicSharedMemorySize, smemBytes);

    zero_state_kernel<<<512, 256>>>();

    dim3 grid(7, 7, B_);
    for (int t = 0; t < T_; t++) {
        step_kernel<<<grid, 256, smemBytes>>>(x, Wk, Uk, bias, out, t, t & 1);
    }

    ln_kernel<<<B_ * T_, 512>>>(out, gamma, beta);
}

// round 3
// speedup vs baseline: 1.3055x; 1.3055x over previous
#include <cuda_runtime.h>
#include <math.h>

#define B_   16
#define T_   24
#define H_   112
#define W_   112
#define CIN  3
#define F_   32
#define FOURF 128
#define HP   56
#define WPd  56
#define D_   (HP*WPd*F_)   // 100352

#define TS      8           // 8x8 output tile
#define HT      10          // h input tile (stride 1, halo)
#define HPITCH  20          // 8 consecutive rows -> distinct bank groups (20*8=5*32)
#define XT      17          // x input tile (stride 2, halo)
#define XPITCH  20

// SMEM layout (floats)
#define UK_SZ    (9*F_*FOURF)            // 36864  (gate-permuted)
#define WK_SZ    (9*CIN*FOURF)           // 3456   (gate-permuted)
#define BI_SZ    FOURF                   // 128    (gate-permuted)
#define HS_SZ    (F_*HT*HPITCH)          // 6400
#define XS_SZ    (CIN*XT*XPITCH)         // 1020
#define SM_TOTAL (UK_SZ+WK_SZ+BI_SZ+HS_SZ+XS_SZ)  // 47868 floats = 191472 B

// persistent state + permuted weights (device globals; no runtime allocation)
__device__ float g_h[2][(size_t)B_*HP*WPd*F_];
__device__ float g_c[(size_t)B_*HP*WPd*F_];
__device__ float g_uk[UK_SZ];   // [tap*32+ci][f*4+gate]
__device__ float g_wk[WK_SZ];   // [tap*3+ci][f*4+gate]
__device__ float g_b[BI_SZ];    // [f*4+gate]

__global__ void prep_kernel(const float* __restrict__ Wk,
                            const float* __restrict__ Uk,
                            const float* __restrict__ bias) {
    const int n = B_*HP*WPd*F_;
    for (int i = blockIdx.x*blockDim.x + threadIdx.x; i < n; i += gridDim.x*blockDim.x) {
        g_h[0][i] = 0.0f;
        g_c[i]    = 0.0f;
        if (i < UK_SZ) {
            int tf = i >> 7, ch = i & 127;
            g_uk[tf*128 + (ch & 31)*4 + (ch >> 5)] = Uk[i];
        }
        if (i < WK_SZ) {
            int tf = i >> 7, ch = i & 127;
            g_wk[tf*128 + (ch & 31)*4 + (ch >> 5)] = Wk[i];
        }
        if (i < BI_SZ) {
            g_b[(i & 31)*4 + (i >> 5)] = bias[i];
        }
    }
}

__global__ void __launch_bounds__(256, 1) step_kernel(
    const float* __restrict__ x,     // (B,T,H,W,CIN)
    float* __restrict__ out,         // (B,T,D)
    int t, int parity)
{
    extern __shared__ float sm[];
    float* uk_s = sm;
    float* wk_s = uk_s + UK_SZ;
    float* b_s  = wk_s + WK_SZ;
    float* h_s  = b_s  + BI_SZ;
    float* x_s  = h_s  + HS_SZ;

    const int tid   = threadIdx.x;
    const int tileX = blockIdx.x;   // 0..6
    const int tileY = blockIdx.y;   // 0..6
    const int b     = blockIdx.z;   // 0..15

    const float* h_in  = g_h[parity];
    float*       h_out = g_h[parity ^ 1];

    // ---- stage permuted weights into smem (straight float4 copies) ----
    {
        const float4* g4 = (const float4*)g_uk;
        float4*       s4 = (float4*)uk_s;
        #pragma unroll 4
        for (int i = tid; i < UK_SZ/4; i += 256) s4[i] = g4[i];
    }
    {
        const float4* g4 = (const float4*)g_wk;
        float4*       s4 = (float4*)wk_s;
        for (int i = tid; i < WK_SZ/4; i += 256) s4[i] = g4[i];
    }
    if (tid < FOURF) b_s[tid] = g_b[tid];

    // ---- load x tile with halo (stride-2 SAME: pad_lo=0, pad_hi=1) ----
    {
        const int r0 = tileY * 16, c0 = tileX * 16;
        const float* xt = x + (((size_t)b * T_ + t) * H_) * (size_t)(W_ * CIN);
        for (int i = tid; i < XT*XT*CIN; i += 256) {
            int ci = i % CIN;
            int xx = (i / CIN) % XT;
            int yy = i / (CIN * XT);
            int gr = r0 + yy, gc = c0 + xx;
            float v = (gr < H_ && gc < W_) ? xt[((size_t)gr * W_ + gc) * CIN + ci] : 0.0f;
            x_s[ci * (XT*XPITCH) + yy * XPITCH + xx] = v;
        }
    }

    // ---- load h tile with halo (stride-1 SAME: pad 1) ----
    {
        const int hr0 = tileY * TS - 1, hc0 = tileX * TS - 1;
        const float* hb = h_in + (size_t)b * HP * WPd * F_;
        for (int i = tid; i < HT*HT*F_; i += 256) {
            int f  = i % F_;
            int xx = (i / F_) % HT;
            int yy = i / (F_ * HT);
            int gr = hr0 + yy, gc = hc0 + xx;
            float v = (gr >= 0 && gr < HP && gc >= 0 && gc < WPd)
                        ? hb[((size_t)gr * WPd + gc) * F_ + f] : 0.0f;
            h_s[f * (HT*HPITCH) + yy * HPITCH + xx] = v;
        }
    }
    __syncthreads();

    // ---- conv phase ----
    // thread = (row py, channel f); computes 8 px x 4 gates = 32 accs.
    // lane = (f_sub << 3) | py  -> h row LDS: 8 distinct rows x4 broadcast (conflict-free)
    //                             weight LDS.128: 4 consecutive float4 x8 broadcast (conflict-free)
    const int lane = tid & 31;
    const int py   = lane & 7;
    const int f    = (tid >> 5) * 4 + (lane >> 3);

    float acc[32];
    {
        float4 bv = *(const float4*)&b_s[f * 4];
        #pragma unroll
        for (int px = 0; px < 8; px++) {
            acc[px*4+0] = bv.x; acc[px*4+1] = bv.y;
            acc[px*4+2] = bv.z; acc[px*4+3] = bv.w;
        }
    }

    // input conv: row-cache x (17 wide), reuse across kw
    #pragma unroll
    for (int kh = 0; kh < 3; kh++) {
        #pragma unroll
        for (int ci = 0; ci < CIN; ci++) {
            const float* xr = &x_s[ci * (XT*XPITCH) + (2*py + kh) * XPITCH];
            float xv[17];
            {
                float4 a0 = *(const float4*)(xr + 0);
                float4 a1 = *(const float4*)(xr + 4);
                float4 a2 = *(const float4*)(xr + 8);
                float4 a3 = *(const float4*)(xr + 12);
                xv[0]=a0.x; xv[1]=a0.y; xv[2]=a0.z; xv[3]=a0.w;
                xv[4]=a1.x; xv[5]=a1.y; xv[6]=a1.z; xv[7]=a1.w;
                xv[8]=a2.x; xv[9]=a2.y; xv[10]=a2.z; xv[11]=a2.w;
                xv[12]=a3.x; xv[13]=a3.y; xv[14]=a3.z; xv[15]=a3.w;
                xv[16]=xr[16];
            }
            #pragma unroll
            for (int kw = 0; kw < 3; kw++) {
                float4 w = *(const float4*)&wk_s[((kh*3 + kw)*CIN + ci) * FOURF + f*4];
                #pragma unroll
                for (int px = 0; px < 8; px++) {
                    float v = xv[2*px + kw];
                    acc[px*4+0] = fmaf(v, w.x, acc[px*4+0]);
                    acc[px*4+1] = fmaf(v, w.y, acc[px*4+1]);
                    acc[px*4+2] = fmaf(v, w.z, acc[px*4+2]);
                    acc[px*4+3] = fmaf(v, w.w, acc[px*4+3]);
                }
            }
        }
    }

    // recurrent conv: row-cache h (10 wide), reuse across kw
    #pragma unroll
    for (int kh = 0; kh < 3; kh++) {
        #pragma unroll 2
        for (int ci = 0; ci < F_; ci++) {
            const float* hr = &h_s[ci * (HT*HPITCH) + (py + kh) * HPITCH];
            float hv[10];
            {
                float4 a0 = *(const float4*)(hr + 0);
                float4 a1 = *(const float4*)(hr + 4);
                float2 a2 = *(const float2*)(hr + 8);
                hv[0]=a0.x; hv[1]=a0.y; hv[2]=a0.z; hv[3]=a0.w;
                hv[4]=a1.x; hv[5]=a1.y; hv[6]=a1.z; hv[7]=a1.w;
                hv[8]=a2.x; hv[9]=a2.y;
            }
            #pragma unroll
            for (int kw = 0; kw < 3; kw++) {
                float4 w = *(const float4*)&uk_s[((kh*3 + kw)*F_ + ci) * FOURF + f*4];
                #pragma unroll
                for (int px = 0; px < 8; px++) {
                    float v = hv[px + kw];
                    acc[px*4+0] = fmaf(v, w.x, acc[px*4+0]);
                    acc[px*4+1] = fmaf(v, w.y, acc[px*4+1]);
                    acc[px*4+2] = fmaf(v, w.z, acc[px*4+2]);
                    acc[px*4+3] = fmaf(v, w.w, acc[px*4+3]);
                }
            }
        }
    }

    // ---- gate phase: directly from accumulators (no smem exchange) ----
    {
        const int hp0 = tileY * TS, wp0 = tileX * TS;
        float* cb  = g_c   + (size_t)b * HP * WPd * F_;
        float* hob = h_out + (size_t)b * HP * WPd * F_;
        float* ob  = out   + ((size_t)b * T_ + t) * D_;
        size_t gbase = ((size_t)(hp0 + py) * WPd + wp0) * F_ + f;
        #pragma unroll
        for (int px = 0; px < 8; px++) {
            size_t g = gbase + (size_t)px * F_;
            float zi = acc[px*4+0];
            float zf = acc[px*4+1];
            float zc = acc[px*4+2];
            float zo = acc[px*4+3];
            float iG = __saturatef(fmaf(zi, 0.2f, 0.5f));
            float fG = __saturatef(fmaf(zf, 0.2f, 0.5f));
            float oG = __saturatef(fmaf(zo, 0.2f, 0.5f));
            float cn = fG * cb[g] + iG * tanhf(zc);
            float hn = oG * tanhf(cn);
            cb[g]  = cn;
            hob[g] = hn;
            ob[g]  = hn;
        }
    }
}

__global__ void __launch_bounds__(512) ln_kernel(
    float* __restrict__ y, const float* __restrict__ gamma, const float* __restrict__ beta)
{
    __shared__ float s_sum[16], s_sum2[16], s_stat[2];
    float* row = y + (size_t)blockIdx.x * D_;
    float s = 0.f, s2 = 0.f;
    for (int i = threadIdx.x; i < D_; i += blockDim.x) {
        float v = row[i];
        s += v;
        s2 = fmaf(v, v, s2);
    }
    #pragma unroll
    for (int o = 16; o > 0; o >>= 1) {
        s  += __shfl_xor_sync(0xFFFFFFFFu, s,  o);
        s2 += __shfl_xor_sync(0xFFFFFFFFu, s2, o);
    }
    int w = threadIdx.x >> 5, l = threadIdx.x & 31;
    if (l == 0) { s_sum[w] = s; s_sum2[w] = s2; }
    __syncthreads();
    if (w == 0) {
        s  = (l < 16) ? s_sum[l]  : 0.f;
        s2 = (l < 16) ? s_sum2[l] : 0.f;
        #pragma unroll
        for (int o = 8; o > 0; o >>= 1) {
            s  += __shfl_xor_sync(0xFFFFFFFFu, s,  o);
            s2 += __shfl_xor_sync(0xFFFFFFFFu, s2, o);
        }
        if (l == 0) {
            float mu  = s * (1.0f / D_);
            float var = s2 * (1.0f / D_) - mu * mu;
            s_stat[0] = mu;
            s_stat[1] = rsqrtf(var + 1e-3f);
        }
    }
    __syncthreads();
    float mu = s_stat[0], rs = s_stat[1];
    for (int i = threadIdx.x; i < D_; i += blockDim.x) {
        row[i] = (row[i] - mu) * rs * gamma[i] + beta[i];
    }
}

extern "C" void kernel_launch(void* const* d_in, const int* in_sizes, int n_in,
                              void* d_out, int out_size)
{
    const float* x     = (const float*)d_in[0];
    const float* Wk    = (const float*)d_in[1];
    const float* Uk    = (const float*)d_in[2];
    const float* bias  = (const float*)d_in[3];
    const float* gamma = (const float*)d_in[4];
    const float* beta  = (const float*)d_in[5];
    float* out = (float*)d_out;

    const int smemBytes = SM_TOTAL * (int)sizeof(float);   // 191472
    cudaFuncSetAttribute(step_kernel, cudaFuncAttributeMaxDynamicSharedMemorySize, smemBytes);

    prep_kernel<<<512, 256>>>(Wk, Uk, bias);

    dim3 grid(7, 7, B_);
    for (int t = 0; t < T_; t++) {
        step_kernel<<<grid, 256, smemBytes>>>(x, out, t, t & 1);
    }

    ln_kernel<<<B_ * T_, 512>>>(out, gamma, beta);
}

// round 6
// speedup vs baseline: 3.5223x; 2.6980x over previous
#include <cuda_runtime.h>
#include <cuda_bf16.h>
#include <cstdint>

#define B_    16
#define T_    24
#define HH    112
#define WW    112
#define F_    32
#define HP    56
#define NPOS  (HP*HP)       // 3136
#define GPOS  (B_*NPOS)     // 50176
#define D_    (NPOS*F_)     // 100352
#define NKS   20            // k16 steps (288 h + 32 x-pad)
#define NTILES (GPOS/128)   // 392

// B fragment arrays: [ks 20][nfg 16][lane 32][reg 2] u32
#define BFRAG_N   (NKS*16*32*2)     // 20480 u32 = 81920 B
#define BFRAG_BYTES 81920

// SMEM layout (bytes)
#define SM_BIAS  0
#define SM_MBAR  512
#define SM_BHI   1024
#define SM_BLO   (1024 + BFRAG_BYTES)
#define SM_TOTAL (1024 + 2*BFRAG_BYTES)   // 164864

// ---------------- helpers ----------------
__device__ __forceinline__ uint32_t smem_to_u32(const void* p) {
    uint32_t a;
    asm("{ .reg .u64 t; cvta.to.shared.u64 t, %1; cvt.u32.u64 %0, t; }" : "=r"(a) : "l"(p));
    return a;
}
__device__ __forceinline__ float tanh_fast(float x) {
    float y; asm("tanh.approx.f32 %0, %1;" : "=f"(y) : "f"(x)); return y;
}
#define MBARRIER_INIT(mbar, cnt) \
    asm volatile("mbarrier.init.shared.b64 [%0], %1;" :: "r"((uint32_t)(mbar)), "r"((uint32_t)(cnt)) : "memory")
#define MBARRIER_EXPECT_TX(mbar, tx) \
    asm volatile("mbarrier.arrive.expect_tx.shared.b64 _, [%0], %1;" :: "r"((uint32_t)(mbar)), "r"((uint32_t)(tx)) : "memory")
#define MBARRIER_WAIT_PARITY(mbar, par) do { \
    uint32_t _m = (uint32_t)(mbar); uint32_t _p = (uint32_t)(par); uint32_t _done; \
    asm volatile("{\n\t.reg .pred p;\n\tmbarrier.try_wait.parity.acquire.cta.shared::cta.b64 p, [%1], %2;\n\tselp.b32 %0, 1, 0, p;\n\t}" \
        : "=r"(_done) : "r"(_m), "r"(_p) : "memory"); \
    if (!_done) { \
        asm volatile("{\n\t.reg .pred P1;\n\tWL_%=:\n\tmbarrier.try_wait.parity.acquire.cta.shared::cta.b64 P1, [%0], %1, 0x989680;\n\t@P1 bra.uni WD_%=;\n\tbra.uni WL_%=;\n\tWD_%=:\n\t}" \
            :: "r"(_m), "r"(_p) : "memory"); \
    } \
} while (0)

__device__ __forceinline__ void mma16816(float* c, const uint32_t* a, const uint32_t* b) {
    asm volatile(
        "mma.sync.aligned.m16n8k16.row.col.f32.bf16.bf16.f32 "
        "{%0,%1,%2,%3}, {%4,%5,%6,%7}, {%8,%9}, {%0,%1,%2,%3};"
        : "+f"(c[0]), "+f"(c[1]), "+f"(c[2]), "+f"(c[3])
        : "r"(a[0]), "r"(a[1]), "r"(a[2]), "r"(a[3]), "r"(b[0]), "r"(b[1]));
}

// ---------------- persistent state ----------------
__device__ __align__(128) uint16_t g_hhi[2][(size_t)GPOS * F_];
__device__ __align__(128) uint16_t g_hlo[2][(size_t)GPOS * F_];
__device__ __align__(128) float    g_c[(size_t)GPOS * F_];
__device__ __align__(128) uint32_t g_BfragHi[BFRAG_N];
__device__ __align__(128) uint32_t g_BfragLo[BFRAG_N];
__device__ __align__(128) float    g_bias[128];

// weight for GEMM column ch (original channel = gate*32+feature), row k
__device__ __forceinline__ float wt(int k, int ch, const float* Wk, const float* Uk) {
    if (k < 288) return Uk[(size_t)((k >> 5) * F_ + (k & 31)) * 128 + ch];
    if (k < 315) return Wk[(size_t)(k - 288) * 128 + ch];
    return 0.0f;
}

__global__ void prep_kernel(const float* __restrict__ Wk,
                            const float* __restrict__ Uk,
                            const float* __restrict__ bias) {
    int i0 = blockIdx.x * blockDim.x + threadIdx.x;
    int stride = gridDim.x * blockDim.x;
    for (size_t i = i0; i < (size_t)GPOS * F_; i += stride) {
        g_hhi[0][i] = 0; g_hlo[0][i] = 0; g_c[i] = 0.0f;
    }
    for (int i = i0; i < BFRAG_N; i += stride) {
        int j   = i & 1;          // b-frag reg (k +0 / +8)
        int l   = (i >> 1) & 31;  // lane
        int nfg = (i >> 6) & 15;  // global n8-frag
        int ks  = i >> 10;        // k-step
        int k0  = ks * 16 + (l & 3) * 2 + j * 8;
        // column mapping: physical warp-local col -> (feature, gate)
        int col8 = l >> 2;             // col within n8
        int a    = nfg & 7;
        int F0   = (nfg >= 8) ? 16 : 0;
        int q    = col8 >> 1, e = col8 & 1;
        int f    = F0 + 4 * q + (a & 3);
        int g    = 2 * (a >> 2) + e;
        int ch   = g * 32 + f;
        float w0 = wt(k0, ch, Wk, Uk);
        float w1 = wt(k0 + 1, ch, Wk, Uk);
        __nv_bfloat16 h0 = __float2bfloat16(w0);
        __nv_bfloat16 h1 = __float2bfloat16(w1);
        __nv_bfloat16 l0 = __float2bfloat16(w0 - __bfloat162float(h0));
        __nv_bfloat16 l1 = __float2bfloat16(w1 - __bfloat162float(h1));
        g_BfragHi[i] = (uint32_t)__bfloat16_as_ushort(h0) | ((uint32_t)__bfloat16_as_ushort(h1) << 16);
        g_BfragLo[i] = (uint32_t)__bfloat16_as_ushort(l0) | ((uint32_t)__bfloat16_as_ushort(l1) << 16);
    }
    if (i0 < 128) g_bias[i0] = bias[i0];
}

// pack two fp32 into bf16x2 hi and lo parts
__device__ __forceinline__ void pack_hilo(float v0, float v1, uint32_t& hi, uint32_t& lo) {
    __nv_bfloat16 h0 = __float2bfloat16(v0);
    __nv_bfloat16 h1 = __float2bfloat16(v1);
    __nv_bfloat16 l0 = __float2bfloat16(v0 - __bfloat162float(h0));
    __nv_bfloat16 l1 = __float2bfloat16(v1 - __bfloat162float(h1));
    hi = (uint32_t)__bfloat16_as_ushort(h0) | ((uint32_t)__bfloat16_as_ushort(h1) << 16);
    lo = (uint32_t)__bfloat16_as_ushort(l0) | ((uint32_t)__bfloat16_as_ushort(l1) << 16);
}

// ---------------- per-step GEMM kernel ----------------
__global__ void __launch_bounds__(256, 1) step_kernel(
    const float* __restrict__ x, float* __restrict__ out, int t, int parity)
{
    extern __shared__ char smem[];
    float* bias_s = (float*)(smem + SM_BIAS);
    const uint32_t mbar = smem_to_u32(smem) + SM_MBAR;
    const uint32_t* bHiS = (const uint32_t*)(smem + SM_BHI);
    const uint32_t* bLoS = (const uint32_t*)(smem + SM_BLO);

    const int tid  = threadIdx.x;
    const int wid  = tid >> 5;
    const int lane = tid & 31;
    const int tig  = lane & 3;
    const int rl   = lane >> 2;
    const int m_base = (wid >> 1) * 32;
    const int nw     = wid & 1;

    if (tid == 0) MBARRIER_INIT(mbar, 1);
    if (tid < 128) bias_s[tid] = g_bias[tid];
    __syncthreads();
    if (tid == 0) {
        MBARRIER_EXPECT_TX(mbar, 2 * BFRAG_BYTES);
        asm volatile("cp.async.bulk.shared::cluster.global.mbarrier::complete_tx::bytes [%0], [%1], %2, [%3];"
                     :: "r"(smem_to_u32(smem) + SM_BHI), "l"((const void*)g_BfragHi), "r"(BFRAG_BYTES), "r"(mbar) : "memory");
        asm volatile("cp.async.bulk.shared::cluster.global.mbarrier::complete_tx::bytes [%0], [%1], %2, [%3];"
                     :: "r"(smem_to_u32(smem) + SM_BLO), "l"((const void*)g_BfragLo), "r"(BFRAG_BYTES), "r"(mbar) : "memory");
    }

    // per-thread row info (4 rows: mtile{0,1} x {r, r+8})
    int pr[4], pc[4], bo[4];
    uint32_t xoff[4];
    #pragma unroll
    for (int i = 0; i < 4; i++) {
        int m  = m_base + rl + ((i >> 1) ? 16 : 0) + ((i & 1) ? 8 : 0);
        int gp = blockIdx.x * 128 + m;
        int b  = gp / NPOS;
        int p  = gp - b * NPOS;
        pr[i] = p / HP;
        pc[i] = p - pr[i] * HP;
        bo[i] = b * NPOS;
        xoff[i] = (uint32_t)(b * T_ + t) * (HH * WW * 3);
    }

    float acc[2][8][4];
    #pragma unroll
    for (int mt = 0; mt < 2; mt++)
        #pragma unroll
        for (int nf = 0; nf < 8; nf++)
            #pragma unroll
            for (int q = 0; q < 4; q++) acc[mt][nf][q] = 0.0f;

    const uint16_t* hhi = g_hhi[parity];
    const uint16_t* hlo = g_hlo[parity];

    MBARRIER_WAIT_PARITY(mbar, 0);

    // ---- recurrent taps (ks 0..17) ----
    #pragma unroll 1
    for (int tap = 0; tap < 9; tap++) {
        const int dr = tap / 3 - 1, dc = tap % 3 - 1;
        int off[4]; bool ok[4];
        #pragma unroll
        for (int i = 0; i < 4; i++) {
            int hr = pr[i] + dr, hc = pc[i] + dc;
            ok[i]  = ((unsigned)hr < HP) && ((unsigned)hc < HP);
            off[i] = (bo[i] + hr * HP + hc) * F_;
        }
        #pragma unroll
        for (int kh = 0; kh < 2; kh++) {
            const int ks = tap * 2 + kh;
            const int cb = kh * 16 + tig * 2;
            uint32_t ahi[2][4], alo[2][4];
            #pragma unroll
            for (int mt = 0; mt < 2; mt++) {
                #pragma unroll
                for (int rr = 0; rr < 2; rr++) {
                    int i = 2 * mt + rr;
                    ahi[mt][rr]     = ok[i] ? *(const uint32_t*)(hhi + off[i] + cb)     : 0u;
                    ahi[mt][rr + 2] = ok[i] ? *(const uint32_t*)(hhi + off[i] + cb + 8) : 0u;
                    alo[mt][rr]     = ok[i] ? *(const uint32_t*)(hlo + off[i] + cb)     : 0u;
                    alo[mt][rr + 2] = ok[i] ? *(const uint32_t*)(hlo + off[i] + cb + 8) : 0u;
                }
            }
            #pragma unroll
            for (int nf = 0; nf < 8; nf++) {
                int fi = ((ks * 16 + nw * 8 + nf) * 32 + lane) * 2;
                uint2 bhv = *(const uint2*)(bHiS + fi);
                uint2 blv = *(const uint2*)(bLoS + fi);
                uint32_t bh[2] = {bhv.x, bhv.y};
                uint32_t bl[2] = {blv.x, blv.y};
                #pragma unroll
                for (int mt = 0; mt < 2; mt++) {
                    mma16816(acc[mt][nf], ahi[mt], bh);
                    mma16816(acc[mt][nf], ahi[mt], bl);
                    mma16816(acc[mt][nf], alo[mt], bh);
                }
            }
        }
    }

    // ---- input-conv taps (ks 18,19): x gathered + converted on the fly ----
    #pragma unroll 1
    for (int kh = 0; kh < 2; kh++) {
        const int ks = 18 + kh;
        const int jb = kh * 16 + tig * 2;
        uint32_t ahi[2][4], alo[2][4];
        #pragma unroll
        for (int mt = 0; mt < 2; mt++) {
            #pragma unroll
            for (int rr = 0; rr < 2; rr++) {
                int i = 2 * mt + rr;
                #pragma unroll
                for (int part = 0; part < 2; part++) {
                    float v[2];
                    #pragma unroll
                    for (int e = 0; e < 2; e++) {
                        int j = jb + part * 8 + e;
                        float val = 0.0f;
                        if (j < 27) {
                            int t3 = (j * 11) >> 5;          // j/3
                            int c3 = j - t3 * 3;
                            int kr = (t3 * 11) >> 5;          // t3/3
                            int kc = t3 - kr * 3;
                            int xr = 2 * pr[i] + kr;
                            int xc = 2 * pc[i] + kc;
                            if (xr < HH && xc < WW)
                                val = x[xoff[i] + (uint32_t)xr * (WW * 3) + xc * 3 + c3];
                        }
                        v[e] = val;
                    }
                    pack_hilo(v[0], v[1], ahi[mt][rr + 2 * part], alo[mt][rr + 2 * part]);
                }
            }
        }
        #pragma unroll
        for (int nf = 0; nf < 8; nf++) {
            int fi = ((ks * 16 + nw * 8 + nf) * 32 + lane) * 2;
            uint2 bhv = *(const uint2*)(bHiS + fi);
            uint2 blv = *(const uint2*)(bLoS + fi);
            uint32_t bh[2] = {bhv.x, bhv.y};
            uint32_t bl[2] = {blv.x, blv.y};
            #pragma unroll
            for (int mt = 0; mt < 2; mt++) {
                mma16816(acc[mt][nf], ahi[mt], bh);
                mma16816(acc[mt][nf], ahi[mt], bl);
                mma16816(acc[mt][nf], alo[mt], bh);
            }
        }
    }

    // ---- epilogue: gates + state update (register-local, no exchange) ----
    const int F0 = nw * 16;
    const int fb = F0 + 4 * tig;          // 4 contiguous features
    uint16_t* hhiO = g_hhi[parity ^ 1];
    uint16_t* hloO = g_hlo[parity ^ 1];
    #pragma unroll
    for (int mt = 0; mt < 2; mt++) {
        #pragma unroll
        for (int hf = 0; hf < 2; hf++) {
            int m  = m_base + rl + mt * 16 + hf * 8;
            int gp = blockIdx.x * 128 + m;
            int b  = gp / NPOS;
            int p  = gp - b * NPOS;
            size_t sidx = (size_t)gp * F_ + fb;
            float4 cold = *(const float4*)(g_c + sidx);
            float cv[4] = {cold.x, cold.y, cold.z, cold.w};
            float hv[4];
            uint16_t hh16[4], hl16[4];
            #pragma unroll
            for (int a0 = 0; a0 < 4; a0++) {
                int f = fb + a0;
                float zi = acc[mt][a0][2 * hf + 0]     + bias_s[f];
                float zf = acc[mt][a0][2 * hf + 1]     + bias_s[32 + f];
                float zc = acc[mt][a0 + 4][2 * hf + 0] + bias_s[64 + f];
                float zo = acc[mt][a0 + 4][2 * hf + 1] + bias_s[96 + f];
                float iG = __saturatef(fmaf(zi, 0.2f, 0.5f));
                float fG = __saturatef(fmaf(zf, 0.2f, 0.5f));
                float oG = __saturatef(fmaf(zo, 0.2f, 0.5f));
                float cn = fG * cv[a0] + iG * tanh_fast(zc);
                float hn = oG * tanh_fast(cn);
                cv[a0] = cn; hv[a0] = hn;
                __nv_bfloat16 hb = __float2bfloat16(hn);
                __nv_bfloat16 lb = __float2bfloat16(hn - __bfloat162float(hb));
                hh16[a0] = __bfloat16_as_ushort(hb);
                hl16[a0] = __bfloat16_as_ushort(lb);
            }
            *(float4*)(g_c + sidx) = make_float4(cv[0], cv[1], cv[2], cv[3]);
            *(uint64_t*)(hhiO + sidx) = *(const uint64_t*)hh16;
            *(uint64_t*)(hloO + sidx) = *(const uint64_t*)hl16;
            float* ob = out + ((size_t)b * T_ + t) * D_ + (size_t)p * F_ + fb;
            *(float4*)ob = make_float4(hv[0], hv[1], hv[2], hv[3]);
        }
    }
}

// ---------------- LayerNorm ----------------
__global__ void __launch_bounds__(512) ln_kernel(
    float* __restrict__ y, const float* __restrict__ gamma, const float* __restrict__ beta)
{
    __shared__ float s_sum[16], s_sum2[16], s_stat[2];
    float* row = y + (size_t)blockIdx.x * D_;
    float s = 0.f, s2 = 0.f;
    for (int i = threadIdx.x; i < D_; i += blockDim.x) {
        float v = row[i];
        s += v;
        s2 = fmaf(v, v, s2);
    }
    #pragma unroll
    for (int o = 16; o > 0; o >>= 1) {
        s  += __shfl_xor_sync(0xFFFFFFFFu, s,  o);
        s2 += __shfl_xor_sync(0xFFFFFFFFu, s2, o);
    }
    int w = threadIdx.x >> 5, l = threadIdx.x & 31;
    if (l == 0) { s_sum[w] = s; s_sum2[w] = s2; }
    __syncthreads();
    if (w == 0) {
        s  = (l < 16) ? s_sum[l]  : 0.f;
        s2 = (l < 16) ? s_sum2[l] : 0.f;
        #pragma unroll
        for (int o = 8; o > 0; o >>= 1) {
            s  += __shfl_xor_sync(0xFFFFFFFFu, s,  o);
            s2 += __shfl_xor_sync(0xFFFFFFFFu, s2, o);
        }
        if (l == 0) {
            float mu  = s * (1.0f / D_);
            float var = s2 * (1.0f / D_) - mu * mu;
            s_stat[0] = mu;
            s_stat[1] = rsqrtf(var + 1e-3f);
        }
    }
    __syncthreads();
    float mu = s_stat[0], rs = s_stat[1];
    for (int i = threadIdx.x; i < D_; i += blockDim.x) {
        row[i] = (row[i] - mu) * rs * gamma[i] + beta[i];
    }
}

extern "C" void kernel_launch(void* const* d_in, const int* in_sizes, int n_in,
                              void* d_out, int out_size)
{
    const float* x     = (const float*)d_in[0];
    const float* Wk    = (const float*)d_in[1];
    const float* Uk    = (const float*)d_in[2];
    const float* bias  = (const float*)d_in[3];
    const float* gamma = (const float*)d_in[4];
    const float* beta  = (const float*)d_in[5];
    float* out = (float*)d_out;

    cudaFuncSetAttribute(step_kernel, cudaFuncAttributeMaxDynamicSharedMemorySize, SM_TOTAL);

    prep_kernel<<<512, 256>>>(Wk, Uk, bias);

    for (int t = 0; t < T_; t++) {
        step_kernel<<<NTILES, 256, SM_TOTAL>>>(x, out, t, t & 1);
    }

    ln_kernel<<<B_ * T_, 512>>>(out, gamma, beta);
}

// round 8
// speedup vs baseline: 3.6777x; 1.0441x over previous
#include <cuda_runtime.h>
#include <cuda_bf16.h>
#include <cstdint>

#define B_    16
#define T_    24
#define HH    112
#define WW    112
#define F_    32
#define HP    56
#define NPOS  (HP*HP)       // 3136
#define GPOS  (B_*NPOS)     // 50176
#define D_    (NPOS*F_)     // 100352
#define NKS   20            // k16 steps (288 h + 32 x-pad)
#define NTILES (GPOS/128)   // 392

// combined B fragments: [ks 20][nfg 16][lane 32] x uint4 {bh0,bh1,bl0,bl1}
#define BFRAG_QUADS  (NKS*16*32)      // 10240 uint4
#define BFRAG_BYTES  (BFRAG_QUADS*16) // 163840

// SMEM layout (bytes)
#define SM_BIAS  0
#define SM_MBAR  512
#define SM_BF    1024
#define SM_TOTAL (1024 + BFRAG_BYTES)   // 164864

// ---------------- helpers ----------------
__device__ __forceinline__ uint32_t smem_to_u32(const void* p) {
    uint32_t a;
    asm("{ .reg .u64 t; cvta.to.shared.u64 t, %1; cvt.u32.u64 %0, t; }" : "=r"(a) : "l"(p));
    return a;
}
__device__ __forceinline__ float tanh_fast(float x) {
    float y; asm("tanh.approx.f32 %0, %1;" : "=f"(y) : "f"(x)); return y;
}
#define MBARRIER_INIT(mbar, cnt) \
    asm volatile("mbarrier.init.shared.b64 [%0], %1;" :: "r"((uint32_t)(mbar)), "r"((uint32_t)(cnt)) : "memory")
#define MBARRIER_EXPECT_TX(mbar, tx) \
    asm volatile("mbarrier.arrive.expect_tx.shared.b64 _, [%0], %1;" :: "r"((uint32_t)(mbar)), "r"((uint32_t)(tx)) : "memory")
#define MBARRIER_WAIT_PARITY(mbar, par) do { \
    uint32_t _m = (uint32_t)(mbar); uint32_t _p = (uint32_t)(par); uint32_t _done; \
    asm volatile("{\n\t.reg .pred p;\n\tmbarrier.try_wait.parity.acquire.cta.shared::cta.b64 p, [%1], %2;\n\tselp.b32 %0, 1, 0, p;\n\t}" \
        : "=r"(_done) : "r"(_m), "r"(_p) : "memory"); \
    if (!_done) { \
        asm volatile("{\n\t.reg .pred P1;\n\tWL_%=:\n\tmbarrier.try_wait.parity.acquire.cta.shared::cta.b64 P1, [%0], %1, 0x989680;\n\t@P1 bra.uni WD_%=;\n\tbra.uni WL_%=;\n\tWD_%=:\n\t}" \
            :: "r"(_m), "r"(_p) : "memory"); \
    } \
} while (0)

__device__ __forceinline__ void mma16816(float* c, const uint32_t* a, const uint32_t* b) {
    asm volatile(
        "mma.sync.aligned.m16n8k16.row.col.f32.bf16.bf16.f32 "
        "{%0,%1,%2,%3}, {%4,%5,%6,%7}, {%8,%9}, {%0,%1,%2,%3};"
        : "+f"(c[0]), "+f"(c[1]), "+f"(c[2]), "+f"(c[3])
        : "r"(a[0]), "r"(a[1]), "r"(a[2]), "r"(a[3]), "r"(b[0]), "r"(b[1]));
}

// ---------------- persistent state ----------------
__device__ __align__(128) uint16_t g_hhi[2][(size_t)GPOS * F_];
__device__ __align__(128) uint16_t g_hlo[2][(size_t)GPOS * F_];
__device__ __align__(128) float    g_c[(size_t)GPOS * F_];
__device__ __align__(128) uint4    g_Bfrag[BFRAG_QUADS];
__device__ __align__(128) float    g_bias[128];

// weight for GEMM column ch (original channel = gate*32+feature), row k
__device__ __forceinline__ float wt(int k, int ch, const float* Wk, const float* Uk) {
    if (k < 288) return Uk[(size_t)((k >> 5) * F_ + (k & 31)) * 128 + ch];
    if (k < 315) return Wk[(size_t)(k - 288) * 128 + ch];
    return 0.0f;
}

__global__ void prep_kernel(const float* __restrict__ Wk,
                            const float* __restrict__ Uk,
                            const float* __restrict__ bias) {
    int i0 = blockIdx.x * blockDim.x + threadIdx.x;
    int stride = gridDim.x * blockDim.x;
    for (size_t i = i0; i < (size_t)GPOS * F_; i += stride) {
        g_hhi[0][i] = 0; g_hlo[0][i] = 0; g_c[i] = 0.0f;
    }
    for (int i = i0; i < BFRAG_QUADS; i += stride) {
        int l   = i & 31;         // lane
        int nfg = (i >> 5) & 15;  // global n8-frag
        int ks  = i >> 9;         // k-step
        // column mapping: physical warp-local col -> (feature, gate)
        int col8 = l >> 2;
        int a    = nfg & 7;
        int F0   = (nfg >= 8) ? 16 : 0;
        int q    = col8 >> 1, e = col8 & 1;
        int f    = F0 + 4 * q + (a & 3);
        int g    = 2 * (a >> 2) + e;
        int ch   = g * 32 + f;
        uint32_t bh[2], bl[2];
        #pragma unroll
        for (int j = 0; j < 2; j++) {
            int k0 = ks * 16 + (l & 3) * 2 + j * 8;
            float w0 = wt(k0, ch, Wk, Uk);
            float w1 = wt(k0 + 1, ch, Wk, Uk);
            __nv_bfloat16 h0 = __float2bfloat16(w0);
            __nv_bfloat16 h1 = __float2bfloat16(w1);
            __nv_bfloat16 l0 = __float2bfloat16(w0 - __bfloat162float(h0));
            __nv_bfloat16 l1 = __float2bfloat16(w1 - __bfloat162float(h1));
            bh[j] = (uint32_t)__bfloat16_as_ushort(h0) | ((uint32_t)__bfloat16_as_ushort(h1) << 16);
            bl[j] = (uint32_t)__bfloat16_as_ushort(l0) | ((uint32_t)__bfloat16_as_ushort(l1) << 16);
        }
        g_Bfrag[i] = make_uint4(bh[0], bh[1], bl[0], bl[1]);
    }
    if (i0 < 128) g_bias[i0] = bias[i0];
}

// pack two fp32 into bf16x2 hi and lo parts
__device__ __forceinline__ void pack_hilo(float v0, float v1, uint32_t& hi, uint32_t& lo) {
    __nv_bfloat16 h0 = __float2bfloat16(v0);
    __nv_bfloat16 h1 = __float2bfloat16(v1);
    __nv_bfloat16 l0 = __float2bfloat16(v0 - __bfloat162float(h0));
    __nv_bfloat16 l1 = __float2bfloat16(v1 - __bfloat162float(h1));
    hi = (uint32_t)__bfloat16_as_ushort(h0) | ((uint32_t)__bfloat16_as_ushort(h1) << 16);
    lo = (uint32_t)__bfloat16_as_ushort(l0) | ((uint32_t)__bfloat16_as_ushort(l1) << 16);
}

// A buffer layout: buf[mt*8 + 0..3] = Ahi frag, buf[mt*8 + 4..7] = Alo frag
__device__ __forceinline__ void get_off(int tap, const int pr[4], const int pc[4], const int bo[4],
                                        int off[4], bool ok[4]) {
    int dr = tap / 3 - 1, dc = tap % 3 - 1;
    #pragma unroll
    for (int i = 0; i < 4; i++) {
        int hr = pr[i] + dr, hc = pc[i] + dc;
        ok[i]  = ((unsigned)hr < HP) && ((unsigned)hc < HP);
        off[i] = (bo[i] + hr * HP + hc) * F_;
    }
}

__device__ __forceinline__ void load_a(uint32_t buf[16],
                                       const uint16_t* __restrict__ hhi,
                                       const uint16_t* __restrict__ hlo,
                                       const int off[4], const bool ok[4], int kh, int tig) {
    const int cb = kh * 16 + tig * 2;
    #pragma unroll
    for (int mt = 0; mt < 2; mt++) {
        #pragma unroll
        for (int rr = 0; rr < 2; rr++) {
            int i = 2 * mt + rr;
            buf[mt*8 + rr]         = ok[i] ? *(const uint32_t*)(hhi + off[i] + cb)     : 0u;
            buf[mt*8 + rr + 2]     = ok[i] ? *(const uint32_t*)(hhi + off[i] + cb + 8) : 0u;
            buf[mt*8 + 4 + rr]     = ok[i] ? *(const uint32_t*)(hlo + off[i] + cb)     : 0u;
            buf[mt*8 + 4 + rr + 2] = ok[i] ? *(const uint32_t*)(hlo + off[i] + cb + 8) : 0u;
        }
    }
}

__device__ __forceinline__ void do_mmas(float acc[2][8][4], const uint32_t A[16],
                                        const uint4* __restrict__ bF, int ks, int nw, int lane) {
    #pragma unroll
    for (int nf = 0; nf < 8; nf++) {
        uint4 bv = bF[(ks * 16 + nw * 8 + nf) * 32 + lane];
        uint32_t bh[2] = {bv.x, bv.y};
        uint32_t bl[2] = {bv.z, bv.w};
        #pragma unroll
        for (int mt = 0; mt < 2; mt++) {
            mma16816(acc[mt][nf], A + mt * 8, bh);
            mma16816(acc[mt][nf], A + mt * 8, bl);
            mma16816(acc[mt][nf], A + mt * 8 + 4, bh);
        }
    }
}

// ---------------- per-step GEMM kernel ----------------
__global__ void __launch_bounds__(256, 1) step_kernel(
    const float* __restrict__ x, float* __restrict__ out, int t, int parity)
{
    extern __shared__ char smem[];
    float* bias_s = (float*)(smem + SM_BIAS);
    const uint32_t mbar = smem_to_u32(smem) + SM_MBAR;
    const uint4* bF = (const uint4*)(smem + SM_BF);

    const int tid  = threadIdx.x;
    const int wid  = tid >> 5;
    const int lane = tid & 31;
    const int tig  = lane & 3;
    const int rl   = lane >> 2;
    const int m_base = (wid >> 1) * 32;
    const int nw     = wid & 1;

    if (tid == 0) MBARRIER_INIT(mbar, 1);
    if (tid < 128) bias_s[tid] = g_bias[tid];
    __syncthreads();
    if (tid == 0) {
        MBARRIER_EXPECT_TX(mbar, BFRAG_BYTES);
        asm volatile("cp.async.bulk.shared::cluster.global.mbarrier::complete_tx::bytes [%0], [%1], %2, [%3];"
                     :: "r"(smem_to_u32(smem) + SM_BF), "l"((const void*)g_Bfrag), "r"(BFRAG_BYTES), "r"(mbar) : "memory");
    }

    // per-thread row info (4 rows: mtile{0,1} x {r, r+8})
    int pr[4], pc[4], bo[4];
    uint32_t xoff[4];
    #pragma unroll
    for (int i = 0; i < 4; i++) {
        int m  = m_base + rl + ((i >> 1) ? 16 : 0) + ((i & 1) ? 8 : 0);
        int gp = blockIdx.x * 128 + m;
        int b  = gp / NPOS;
        int p  = gp - b * NPOS;
        pr[i] = p / HP;
        pc[i] = p - pr[i] * HP;
        bo[i] = b * NPOS;
        xoff[i] = (uint32_t)(b * T_ + t) * (HH * WW * 3);
    }

    float acc[2][8][4];
    #pragma unroll
    for (int mt = 0; mt < 2; mt++)
        #pragma unroll
        for (int nf = 0; nf < 8; nf++)
            #pragma unroll
            for (int q = 0; q < 4; q++) acc[mt][nf][q] = 0.0f;

    const uint16_t* hhi = g_hhi[parity];
    const uint16_t* hlo = g_hlo[parity];

    // ---- software-pipelined recurrent taps ----
    int offc[4], offn[4];
    bool okc[4], okn[4];
    uint32_t A0[16], A1[16];

    get_off(0, pr, pc, bo, offc, okc);
    load_a(A0, hhi, hlo, offc, okc, 0, tig);     // overlaps the B bulk copy

    MBARRIER_WAIT_PARITY(mbar, 0);

    #pragma unroll 1
    for (int tap = 0; tap < 9; tap++) {
        load_a(A1, hhi, hlo, offc, okc, 1, tig);           // prefetch kh=1
        do_mmas(acc, A0, bF, 2 * tap, nw, lane);
        if (tap < 8) {
            get_off(tap + 1, pr, pc, bo, offn, okn);
            load_a(A0, hhi, hlo, offn, okn, 0, tig);       // prefetch next tap kh=0
            #pragma unroll
            for (int i = 0; i < 4; i++) { offc[i] = offn[i]; okc[i] = okn[i]; }
        }
        do_mmas(acc, A1, bF, 2 * tap + 1, nw, lane);
    }

    // ---- input-conv taps (ks 18,19): x gathered + converted on the fly ----
    #pragma unroll 1
    for (int kh = 0; kh < 2; kh++) {
        const int jb = kh * 16 + tig * 2;
        uint32_t AX[16];
        #pragma unroll
        for (int mt = 0; mt < 2; mt++) {
            #pragma unroll
            for (int rr = 0; rr < 2; rr++) {
                int i = 2 * mt + rr;
                #pragma unroll
                for (int part = 0; part < 2; part++) {
                    float v[2];
                    #pragma unroll
                    for (int e = 0; e < 2; e++) {
                        int j = jb + part * 8 + e;
                        float val = 0.0f;
                        if (j < 27) {
                            int t3 = (j * 11) >> 5;          // j/3
                            int c3 = j - t3 * 3;
                            int kr = (t3 * 11) >> 5;          // t3/3
                            int kc = t3 - kr * 3;
                            int xr = 2 * pr[i] + kr;
                            int xc = 2 * pc[i] + kc;
                            if (xr < HH && xc < WW)
                                val = x[xoff[i] + (uint32_t)xr * (WW * 3) + xc * 3 + c3];
                        }
                        v[e] = val;
                    }
                    pack_hilo(v[0], v[1], AX[mt*8 + rr + 2*part], AX[mt*8 + 4 + rr + 2*part]);
                }
            }
        }
        do_mmas(acc, AX, bF, 18 + kh, nw, lane);
    }

    // ---- epilogue: gates + state update (register-local, no exchange) ----
    const int F0 = nw * 16;
    const int fb = F0 + 4 * tig;          // 4 contiguous features
    uint16_t* hhiO = g_hhi[parity ^ 1];
    uint16_t* hloO = g_hlo[parity ^ 1];
    #pragma unroll
    for (int mt = 0; mt < 2; mt++) {
        #pragma unroll
        for (int hf = 0; hf < 2; hf++) {
            int m  = m_base + rl + mt * 16 + hf * 8;
            int gp = blockIdx.x * 128 + m;
            int b  = gp / NPOS;
            int p  = gp - b * NPOS;
            size_t sidx = (size_t)gp * F_ + fb;
            float4 cold = *(const float4*)(g_c + sidx);
            float cv[4] = {cold.x, cold.y, cold.z, cold.w};
            float hv[4];
            uint16_t hh16[4], hl16[4];
            #pragma unroll
            for (int a0 = 0; a0 < 4; a0++) {
                int f = fb + a0;
                float zi = acc[mt][a0][2 * hf + 0]     + bias_s[f];
                float zf = acc[mt][a0][2 * hf + 1]     + bias_s[32 + f];
                float zc = acc[mt][a0 + 4][2 * hf + 0] + bias_s[64 + f];
                float zo = acc[mt][a0 + 4][2 * hf + 1] + bias_s[96 + f];
                float iG = __saturatef(fmaf(zi, 0.2f, 0.5f));
                float fG = __saturatef(fmaf(zf, 0.2f, 0.5f));
                float oG = __saturatef(fmaf(zo, 0.2f, 0.5f));
                float cn = fG * cv[a0] + iG * tanh_fast(zc);
                float hn = oG * tanh_fast(cn);
                cv[a0] = cn; hv[a0] = hn;
                __nv_bfloat16 hb = __float2bfloat16(hn);
                __nv_bfloat16 lb = __float2bfloat16(hn - __bfloat162float(hb));
                hh16[a0] = __bfloat16_as_ushort(hb);
                hl16[a0] = __bfloat16_as_ushort(lb);
            }
            *(float4*)(g_c + sidx) = make_float4(cv[0], cv[1], cv[2], cv[3]);
            *(uint64_t*)(hhiO + sidx) = *(const uint64_t*)hh16;
            *(uint64_t*)(hloO + sidx) = *(const uint64_t*)hl16;
            float* ob = out + ((size_t)b * T_ + t) * D_ + (size_t)p * F_ + fb;
            *(float4*)ob = make_float4(hv[0], hv[1], hv[2], hv[3]);
        }
    }
}

// ---------------- LayerNorm ----------------
__global__ void __launch_bounds__(512) ln_kernel(
    float* __restrict__ y, const float* __restrict__ gamma, const float* __restrict__ beta)
{
    __shared__ float s_sum[16], s_sum2[16], s_stat[2];
    float* row = y + (size_t)blockIdx.x * D_;
    float s = 0.f, s2 = 0.f;
    for (int i = threadIdx.x; i < D_; i += blockDim.x) {
        float v = row[i];
        s += v;
        s2 = fmaf(v, v, s2);
    }
    #pragma unroll
    for (int o = 16; o > 0; o >>= 1) {
        s  += __shfl_xor_sync(0xFFFFFFFFu, s,  o);
        s2 += __shfl_xor_sync(0xFFFFFFFFu, s2, o);
    }
    int w = threadIdx.x >> 5, l = threadIdx.x & 31;
    if (l == 0) { s_sum[w] = s; s_sum2[w] = s2; }
    __syncthreads();
    if (w == 0) {
        s  = (l < 16) ? s_sum[l]  : 0.f;
        s2 = (l < 16) ? s_sum2[l] : 0.f;
        #pragma unroll
        for (int o = 8; o > 0; o >>= 1) {
            s  += __shfl_xor_sync(0xFFFFFFFFu, s,  o);
            s2 += __shfl_xor_sync(0xFFFFFFFFu, s2, o);
        }
        if (l == 0) {
            float mu  = s * (1.0f / D_);
            float var = s2 * (1.0f / D_) - mu * mu;
            s_stat[0] = mu;
            s_stat[1] = rsqrtf(var + 1e-3f);
        }
    }
    __syncthreads();
    float mu = s_stat[0], rs = s_stat[1];
    for (int i = threadIdx.x; i < D_; i += blockDim.x) {
        row[i] = (row[i] - mu) * rs * gamma[i] + beta[i];
    }
}

extern "C" void kernel_launch(void* const* d_in, const int* in_sizes, int n_in,
                              void* d_out, int out_size)
{
    const float* x     = (const float*)d_in[0];
    const float* Wk    = (const float*)d_in[1];
    const float* Uk    = (const float*)d_in[2];
    const float* bias  = (const float*)d_in[3];
    const float* gamma = (const float*)d_in[4];
    const float* beta  = (const float*)d_in[5];
    float* out = (float*)d_out;

    cudaFuncSetAttribute(step_kernel, cudaFuncAttributeMaxDynamicSharedMemorySize, SM_TOTAL);

    prep_kernel<<<512, 256>>>(Wk, Uk, bias);

    for (int t = 0; t < T_; t++) {
        step_kernel<<<NTILES, 256, SM_TOTAL>>>(x, out, t, t & 1);
    }

    ln_kernel<<<B_ * T_, 512>>>(out, gamma, beta);
}

// round 12
// speedup vs baseline: 3.7892x; 1.0303x over previous
#include <cuda_runtime.h>
#include <cuda_bf16.h>
#include <cstdint>

#define B_    16
#define T_    24
#define HH    112
#define WW    112
#define F_    32
#define HP    56
#define NPOS  (HP*HP)       // 3136
#define GPOS  (B_*NPOS)     // 50176
#define D_    (NPOS*F_)     // 100352
#define NKS   20            // k16 steps (288 h + 32 x-pad)
#define NTILES (GPOS/128)   // 392

// combined B fragments: [ks 20][nfg 16][lane 32] x uint4 {bh0,bh1,bl0,bl1}
#define BFRAG_QUADS  (NKS*16*32)      // 10240 uint4
#define BFRAG_BYTES  (BFRAG_QUADS*16) // 163840

// SMEM layout (bytes)
#define SM_BIAS  0
#define SM_MBAR  512
#define SM_BF    1024
#define SM_TOTAL (1024 + BFRAG_BYTES)   // 164864

// ---------------- helpers ----------------
__device__ __forceinline__ uint32_t smem_to_u32(const void* p) {
    uint32_t a;
    asm("{ .reg .u64 t; cvta.to.shared.u64 t, %1; cvt.u32.u64 %0, t; }" : "=r"(a) : "l"(p));
    return a;
}
__device__ __forceinline__ float tanh_fast(float x) {
    float y; asm("tanh.approx.f32 %0, %1;" : "=f"(y) : "f"(x)); return y;
}
#define MBARRIER_INIT(mbar, cnt) \
    asm volatile("mbarrier.init.shared.b64 [%0], %1;" :: "r"((uint32_t)(mbar)), "r"((uint32_t)(cnt)) : "memory")
#define MBARRIER_EXPECT_TX(mbar, tx) \
    asm volatile("mbarrier.arrive.expect_tx.shared.b64 _, [%0], %1;" :: "r"((uint32_t)(mbar)), "r"((uint32_t)(tx)) : "memory")
#define MBARRIER_WAIT_PARITY(mbar, par) do { \
    uint32_t _m = (uint32_t)(mbar); uint32_t _p = (uint32_t)(par); uint32_t _done; \
    asm volatile("{\n\t.reg .pred p;\n\tmbarrier.try_wait.parity.acquire.cta.shared::cta.b64 p, [%1], %2;\n\tselp.b32 %0, 1, 0, p;\n\t}" \
        : "=r"(_done) : "r"(_m), "r"(_p) : "memory"); \
    if (!_done) { \
        asm volatile("{\n\t.reg .pred P1;\n\tWL_%=:\n\tmbarrier.try_wait.parity.acquire.cta.shared::cta.b64 P1, [%0], %1, 0x989680;\n\t@P1 bra.uni WD_%=;\n\tbra.uni WL_%=;\n\tWD_%=:\n\t}" \
            :: "r"(_m), "r"(_p) : "memory"); \
    } \
} while (0)

__device__ __forceinline__ void mma16816(float* c, const uint32_t* a, const uint32_t* b) {
    asm volatile(
        "mma.sync.aligned.m16n8k16.row.col.f32.bf16.bf16.f32 "
        "{%0,%1,%2,%3}, {%4,%5,%6,%7}, {%8,%9}, {%0,%1,%2,%3};"
        : "+f"(c[0]), "+f"(c[1]), "+f"(c[2]), "+f"(c[3])
        : "r"(a[0]), "r"(a[1]), "r"(a[2]), "r"(a[3]), "r"(b[0]), "r"(b[1]));
}

// ---------------- persistent state ----------------
__device__ __align__(128) uint16_t g_hhi[2][(size_t)GPOS * F_];
__device__ __align__(128) uint16_t g_hlo[2][(size_t)GPOS * F_];
__device__ __align__(128) float    g_c[(size_t)GPOS * F_];
__device__ __align__(128) uint4    g_Bfrag[BFRAG_QUADS];
__device__ __align__(128) float    g_bias[128];

// weight for GEMM column ch (original channel = gate*32+feature), row k
__device__ __forceinline__ float wt(int k, int ch, const float* Wk, const float* Uk) {
    if (k < 288) return Uk[(size_t)((k >> 5) * F_ + (k & 31)) * 128 + ch];
    if (k < 315) return Wk[(size_t)(k - 288) * 128 + ch];
    return 0.0f;
}

__global__ void prep_kernel(const float* __restrict__ Wk,
                            const float* __restrict__ Uk,
                            const float* __restrict__ bias) {
    int i0 = blockIdx.x * blockDim.x + threadIdx.x;
    int stride = gridDim.x * blockDim.x;
    for (size_t i = i0; i < (size_t)GPOS * F_; i += stride) {
        g_hhi[0][i] = 0; g_hlo[0][i] = 0; g_c[i] = 0.0f;
    }
    for (int i = i0; i < BFRAG_QUADS; i += stride) {
        int l   = i & 31;         // lane
        int nfg = (i >> 5) & 15;  // global n8-frag
        int ks  = i >> 9;         // k-step
        // column mapping: physical warp-local col -> (feature, gate)
        int col8 = l >> 2;
        int a    = nfg & 7;
        int F0   = (nfg >= 8) ? 16 : 0;
        int q    = col8 >> 1, e = col8 & 1;
        int f    = F0 + 4 * q + (a & 3);
        int g    = 2 * (a >> 2) + e;
        int ch   = g * 32 + f;
        uint32_t bh[2], bl[2];
        #pragma unroll
        for (int j = 0; j < 2; j++) {
            int k0 = ks * 16 + (l & 3) * 2 + j * 8;
            float w0 = wt(k0, ch, Wk, Uk);
            float w1 = wt(k0 + 1, ch, Wk, Uk);
            __nv_bfloat16 h0 = __float2bfloat16(w0);
            __nv_bfloat16 h1 = __float2bfloat16(w1);
            __nv_bfloat16 l0 = __float2bfloat16(w0 - __bfloat162float(h0));
            __nv_bfloat16 l1 = __float2bfloat16(w1 - __bfloat162float(h1));
            bh[j] = (uint32_t)__bfloat16_as_ushort(h0) | ((uint32_t)__bfloat16_as_ushort(h1) << 16);
            bl[j] = (uint32_t)__bfloat16_as_ushort(l0) | ((uint32_t)__bfloat16_as_ushort(l1) << 16);
        }
        g_Bfrag[i] = make_uint4(bh[0], bh[1], bl[0], bl[1]);
    }
    if (i0 < 128) g_bias[i0] = bias[i0];
}

// pack two fp32 into bf16x2 hi and lo parts
__device__ __forceinline__ void pack_hilo(float v0, float v1, uint32_t& hi, uint32_t& lo) {
    __nv_bfloat16 h0 = __float2bfloat16(v0);
    __nv_bfloat16 h1 = __float2bfloat16(v1);
    __nv_bfloat16 l0 = __float2bfloat16(v0 - __bfloat162float(h0));
    __nv_bfloat16 l1 = __float2bfloat16(v1 - __bfloat162float(h1));
    hi = (uint32_t)__bfloat16_as_ushort(h0) | ((uint32_t)__bfloat16_as_ushort(h1) << 16);
    lo = (uint32_t)__bfloat16_as_ushort(l0) | ((uint32_t)__bfloat16_as_ushort(l1) << 16);
}

// A buffer layout: buf[0..3] = Ahi frag, buf[4..7] = Alo frag (m16 tile: rows rl, rl+8)
__device__ __forceinline__ void get_off(int tap, const int pr[2], const int pc[2], const int bo[2],
                                        int off[2], bool ok[2]) {
    int dr = tap / 3 - 1, dc = tap % 3 - 1;
    #pragma unroll
    for (int i = 0; i < 2; i++) {
        int hr = pr[i] + dr, hc = pc[i] + dc;
        ok[i]  = ((unsigned)hr < HP) && ((unsigned)hc < HP);
        off[i] = (bo[i] + hr * HP + hc) * F_;
    }
}

__device__ __forceinline__ void load_a(uint32_t buf[8],
                                       const uint16_t* __restrict__ hhi,
                                       const uint16_t* __restrict__ hlo,
                                       const int off[2], const bool ok[2], int kh, int tig) {
    const int cb = kh * 16 + tig * 2;
    #pragma unroll
    for (int rr = 0; rr < 2; rr++) {
        buf[rr]         = ok[rr] ? *(const uint32_t*)(hhi + off[rr] + cb)     : 0u;
        buf[rr + 2]     = ok[rr] ? *(const uint32_t*)(hhi + off[rr] + cb + 8) : 0u;
        buf[4 + rr]     = ok[rr] ? *(const uint32_t*)(hlo + off[rr] + cb)     : 0u;
        buf[4 + rr + 2] = ok[rr] ? *(const uint32_t*)(hlo + off[rr] + cb + 8) : 0u;
    }
}

__device__ __forceinline__ void do_mmas(float acc[8][4], const uint32_t A[8],
                                        const uint4* __restrict__ bF, int ks, int nw, int lane) {
    #pragma unroll
    for (int nf = 0; nf < 8; nf++) {
        uint4 bv = bF[(ks * 16 + nw * 8 + nf) * 32 + lane];
        uint32_t bh[2] = {bv.x, bv.y};
        uint32_t bl[2] = {bv.z, bv.w};
        mma16816(acc[nf], A, bh);
        mma16816(acc[nf], A, bl);
        mma16816(acc[nf], A + 4, bh);
    }
}

// ---------------- per-step GEMM kernel ----------------
__global__ void __launch_bounds__(512, 1) step_kernel(
    const float* __restrict__ x, float* __restrict__ out, int t, int parity)
{
    extern __shared__ char smem[];
    float* bias_s = (float*)(smem + SM_BIAS);
    const uint32_t mbar = smem_to_u32(smem) + SM_MBAR;
    const uint4* bF = (const uint4*)(smem + SM_BF);

    const int tid  = threadIdx.x;
    const int wid  = tid >> 5;
    const int lane = tid & 31;
    const int tig  = lane & 3;
    const int rl   = lane >> 2;
    const int m_base = (wid >> 1) * 16;   // 8 m-warps x 16 rows
    const int nw     = wid & 1;

    if (tid == 0) MBARRIER_INIT(mbar, 1);
    if (tid < 128) bias_s[tid] = g_bias[tid];
    __syncthreads();
    if (tid == 0) {
        MBARRIER_EXPECT_TX(mbar, BFRAG_BYTES);
        asm volatile("cp.async.bulk.shared::cluster.global.mbarrier::complete_tx::bytes [%0], [%1], %2, [%3];"
                     :: "r"(smem_to_u32(smem) + SM_BF), "l"((const void*)g_Bfrag), "r"(BFRAG_BYTES), "r"(mbar) : "memory");
    }

    // per-thread row info (2 rows: rl, rl+8)
    int pr[2], pc[2], bo[2];
    uint32_t xoff[2];
    #pragma unroll
    for (int i = 0; i < 2; i++) {
        int m  = m_base + rl + i * 8;
        int gp = blockIdx.x * 128 + m;
        int b  = gp / NPOS;
        int p  = gp - b * NPOS;
        pr[i] = p / HP;
        pc[i] = p - pr[i] * HP;
        bo[i] = b * NPOS;
        xoff[i] = (uint32_t)(b * T_ + t) * (HH * WW * 3);
    }

    float acc[8][4];
    #pragma unroll
    for (int nf = 0; nf < 8; nf++)
        #pragma unroll
        for (int q = 0; q < 4; q++) acc[nf][q] = 0.0f;

    const uint16_t* hhi = g_hhi[parity];
    const uint16_t* hlo = g_hlo[parity];

    // ---- software-pipelined recurrent taps ----
    int offc[2], offn[2];
    bool okc[2], okn[2];
    uint32_t A0[8], A1[8];

    get_off(0, pr, pc, bo, offc, okc);
    load_a(A0, hhi, hlo, offc, okc, 0, tig);     // overlaps the B bulk copy

    MBARRIER_WAIT_PARITY(mbar, 0);

    #pragma unroll 1
    for (int tap = 0; tap < 9; tap++) {
        load_a(A1, hhi, hlo, offc, okc, 1, tig);           // prefetch kh=1
        do_mmas(acc, A0, bF, 2 * tap, nw, lane);
        if (tap < 8) {
            get_off(tap + 1, pr, pc, bo, offn, okn);
            load_a(A0, hhi, hlo, offn, okn, 0, tig);       // prefetch next tap kh=0
            #pragma unroll
            for (int i = 0; i < 2; i++) { offc[i] = offn[i]; okc[i] = okn[i]; }
        }
        do_mmas(acc, A1, bF, 2 * tap + 1, nw, lane);
    }

    // ---- input-conv taps (ks 18,19): x gathered + converted on the fly ----
    #pragma unroll 1
    for (int kh = 0; kh < 2; kh++) {
        const int jb = kh * 16 + tig * 2;
        uint32_t AX[8];
        #pragma unroll
        for (int rr = 0; rr < 2; rr++) {
            #pragma unroll
            for (int part = 0; part < 2; part++) {
                float v[2];
                #pragma unroll
                for (int e = 0; e < 2; e++) {
                    int j = jb + part * 8 + e;
                    float val = 0.0f;
                    if (j < 27) {
                        int t3 = (j * 11) >> 5;          // j/3
                        int c3 = j - t3 * 3;
                        int kr = (t3 * 11) >> 5;          // t3/3
                        int kc = t3 - kr * 3;
                        int xr = 2 * pr[rr] + kr;
                        int xc = 2 * pc[rr] + kc;
                        if (xr < HH && xc < WW)
                            val = x[xoff[rr] + (uint32_t)xr * (WW * 3) + xc * 3 + c3];
                    }
                    v[e] = val;
                }
                pack_hilo(v[0], v[1], AX[rr + 2 * part], AX[4 + rr + 2 * part]);
            }
        }
        do_mmas(acc, AX, bF, 18 + kh, nw, lane);
    }

    // ---- epilogue: gates + state update (register-local, no exchange) ----
    const int F0 = nw * 16;
    const int fb = F0 + 4 * tig;          // 4 contiguous features
    uint16_t* hhiO = g_hhi[parity ^ 1];
    uint16_t* hloO = g_hlo[parity ^ 1];
    #pragma unroll
    for (int hf = 0; hf < 2; hf++) {
        int m  = m_base + rl + hf * 8;
        int gp = blockIdx.x * 128 + m;
        int b  = gp / NPOS;
        int p  = gp - b * NPOS;
        size_t sidx = (size_t)gp * F_ + fb;
        float4 cold = *(const float4*)(g_c + sidx);
        float cv[4] = {cold.x, cold.y, cold.z, cold.w};
        float hv[4];
        uint16_t hh16[4], hl16[4];
        #pragma unroll
        for (int a0 = 0; a0 < 4; a0++) {
            int f = fb + a0;
            float zi = acc[a0][2 * hf + 0]     + bias_s[f];
            float zf = acc[a0][2 * hf + 1]     + bias_s[32 + f];
            float zc = acc[a0 + 4][2 * hf + 0] + bias_s[64 + f];
            float zo = acc[a0 + 4][2 * hf + 1] + bias_s[96 + f];
            float iG = __saturatef(fmaf(zi, 0.2f, 0.5f));
            float fG = __saturatef(fmaf(zf, 0.2f, 0.5f));
            float oG = __saturatef(fmaf(zo, 0.2f, 0.5f));
            float cn = fG * cv[a0] + iG * tanh_fast(zc);
            float hn = oG * tanh_fast(cn);
            cv[a0] = cn; hv[a0] = hn;
            __nv_bfloat16 hb = __float2bfloat16(hn);
            __nv_bfloat16 lb = __float2bfloat16(hn - __bfloat162float(hb));
            hh16[a0] = __bfloat16_as_ushort(hb);
            hl16[a0] = __bfloat16_as_ushort(lb);
        }
        *(float4*)(g_c + sidx) = make_float4(cv[0], cv[1], cv[2], cv[3]);
        *(uint64_t*)(hhiO + sidx) = *(const uint64_t*)hh16;
        *(uint64_t*)(hloO + sidx) = *(const uint64_t*)hl16;
        float* ob = out + ((size_t)b * T_ + t) * D_ + (size_t)p * F_ + fb;
        *(float4*)ob = make_float4(hv[0], hv[1], hv[2], hv[3]);
    }
}

// ---------------- LayerNorm ----------------
__global__ void __launch_bounds__(512) ln_kernel(
    float* __restrict__ y, const float* __restrict__ gamma, const float* __restrict__ beta)
{
    __shared__ float s_sum[16], s_sum2[16], s_stat[2];
    float* row = y + (size_t)blockIdx.x * D_;
    float s = 0.f, s2 = 0.f;
    for (int i = threadIdx.x; i < D_; i += blockDim.x) {
        float v = row[i];
        s += v;
        s2 = fmaf(v, v, s2);
    }
    #pragma unroll
    for (int o = 16; o > 0; o >>= 1) {
        s  += __shfl_xor_sync(0xFFFFFFFFu, s,  o);
        s2 += __shfl_xor_sync(0xFFFFFFFFu, s2, o);
    }
    int w = threadIdx.x >> 5, l = threadIdx.x & 31;
    if (l == 0) { s_sum[w] = s; s_sum2[w] = s2; }
    __syncthreads();
    if (w == 0) {
        s  = (l < 16) ? s_sum[l]  : 0.f;
        s2 = (l < 16) ? s_sum2[l] : 0.f;
        #pragma unroll
        for (int o = 8; o > 0; o >>= 1) {
            s  += __shfl_xor_sync(0xFFFFFFFFu, s,  o);
            s2 += __shfl_xor_sync(0xFFFFFFFFu, s2, o);
        }
        if (l == 0) {
            float mu  = s * (1.0f / D_);
            float var = s2 * (1.0f / D_) - mu * mu;
            s_stat[0] = mu;
            s_stat[1] = rsqrtf(var + 1e-3f);
        }
    }
    __syncthreads();
    float mu = s_stat[0], rs = s_stat[1];
    for (int i = threadIdx.x; i < D_; i += blockDim.x) {
        row[i] = (row[i] - mu) * rs * gamma[i] + beta[i];
    }
}

extern "C" void kernel_launch(void* const* d_in, const int* in_sizes, int n_in,
                              void* d_out, int out_size)
{
    const float* x     = (const float*)d_in[0];
    const float* Wk    = (const float*)d_in[1];
    const float* Uk    = (const float*)d_in[2];
    const float* bias  = (const float*)d_in[3];
    const float* gamma = (const float*)d_in[4];
    const float* beta  = (const float*)d_in[5];
    float* out = (float*)d_out;

    cudaFuncSetAttribute(step_kernel, cudaFuncAttributeMaxDynamicSharedMemorySize, SM_TOTAL);

    prep_kernel<<<512, 256>>>(Wk, Uk, bias);

    for (int t = 0; t < T_; t++) {
        step_kernel<<<NTILES, 512, SM_TOTAL>>>(x, out, t, t & 1);
    }

    ln_kernel<<<B_ * T_, 512>>>(out, gamma, beta);
}